// round 1
// baseline (speedup 1.0000x reference)
#include <cuda_runtime.h>

// Problem constants
#define BATCH   4
#define SEQLEN  65536
#define RC      32          // residual / dilation channels
#define OC      256         // output channels
#define NBLOCKS 2
#define NLAYERS 10

// -------- scratch (device globals; no allocation allowed) --------
__device__ float g_resid[2][BATCH * RC * SEQLEN];   // ping-pong residual, 2 x 33.5 MB
__device__ float g_skip[BATCH * RC * SEQLEN];       // skip accumulator,  33.5 MB
__device__ float g_hidden[(size_t)BATCH * OC * SEQLEN]; // 268 MB intermediate

// ----------------------------------------------------------------
// Kernel 1: start conv (1 -> 32, 1x1) + zero skip accumulator.
// One thread per (b, c, l) element of resid.
// ----------------------------------------------------------------
__global__ void k_start(const float* __restrict__ x,
                        const float* __restrict__ w,   // (32,1,1)
                        const float* __restrict__ bias) // (32)
{
    size_t idx = (size_t)blockIdx.x * blockDim.x + threadIdx.x;
    if (idx >= (size_t)BATCH * RC * SEQLEN) return;
    int l = (int)(idx % SEQLEN);
    int c = (int)((idx / SEQLEN) % RC);
    int b = (int)(idx / ((size_t)RC * SEQLEN));
    float v = w[c] * x[(size_t)b * SEQLEN + l] + bias[c];
    g_resid[0][idx] = v;
    g_skip[idx] = 0.f;
}

// ----------------------------------------------------------------
// Kernel 2: one gated dilated layer.
//   f = Wf0 * r[l+offA] + Wf1 * r[l+offB] + bf
//   g = Wg0 * r[l+offA] + Wg1 * r[l+offB] + bg
//   lo = f*g
//   r_out = r + Wres*lo + bres ;  skip += Wskip*lo + bskip
// One thread per (b, l), computing all 32 channels in registers.
// ----------------------------------------------------------------
__global__ __launch_bounds__(256)
void k_layer(int ping,
             const float* __restrict__ fw, const float* __restrict__ fb,
             const float* __restrict__ gw, const float* __restrict__ gb,
             const float* __restrict__ rw, const float* __restrict__ rb,
             const float* __restrict__ sw, const float* __restrict__ sb,
             int offA, int offB)
{
    __shared__ float2 swf[RC * RC];   // {tap0, tap1} pairs, [out_c][in_c]
    __shared__ float2 swg[RC * RC];
    __shared__ float2 swrs[RC * RC];  // {res_w, skip_w}
    __shared__ float sbf[RC], sbg[RC], sbr[RC], sbs[RC];

    int tid = threadIdx.x;
    for (int i = tid; i < RC * RC; i += 256) {
        swf[i] = ((const float2*)fw)[i];      // filt_w[c][ci][0..1] contiguous
        swg[i] = ((const float2*)gw)[i];
        swrs[i] = make_float2(rw[i], sw[i]);
    }
    if (tid < RC) { sbf[tid] = fb[tid]; sbg[tid] = gb[tid];
                    sbr[tid] = rb[tid]; sbs[tid] = sb[tid]; }
    __syncthreads();

    int base = blockIdx.x * 256 + tid;        // over BATCH*SEQLEN
    int b = base / SEQLEN;
    int l = base % SEQLEN;

    const float* __restrict__ rin = &g_resid[ping][(size_t)b * RC * SEQLEN];
    float* __restrict__ rout = &g_resid[ping ^ 1][(size_t)b * RC * SEQLEN];
    float* __restrict__ sk = &g_skip[(size_t)b * RC * SEQLEN];

    int la = l + offA;
    int lb = l + offB;
    bool va = (la >= 0) && (la < SEQLEN);
    bool vb = (lb >= 0) && (lb < SEQLEN);

    float f[RC], g[RC];
#pragma unroll
    for (int c = 0; c < RC; c++) { f[c] = sbf[c]; g[c] = sbg[c]; }

#pragma unroll 4
    for (int ci = 0; ci < RC; ci++) {
        float rA = va ? rin[(size_t)ci * SEQLEN + la] : 0.f;
        float rB = vb ? rin[(size_t)ci * SEQLEN + lb] : 0.f;
#pragma unroll
        for (int c = 0; c < RC; c++) {
            float2 wf = swf[c * RC + ci];
            f[c] += wf.x * rA + wf.y * rB;
            float2 wg = swg[c * RC + ci];
            g[c] += wg.x * rA + wg.y * rB;
        }
    }

    float lo[RC];
#pragma unroll
    for (int c = 0; c < RC; c++) lo[c] = f[c] * g[c];

    // reuse f as residual accumulator, g as skip accumulator
#pragma unroll
    for (int c = 0; c < RC; c++) {
        f[c] = rin[(size_t)c * SEQLEN + l] + sbr[c];
        g[c] = sk[(size_t)c * SEQLEN + l] + sbs[c];
    }
#pragma unroll 4
    for (int ci = 0; ci < RC; ci++) {
        float v = lo[ci];
#pragma unroll
        for (int c = 0; c < RC; c++) {
            float2 w = swrs[c * RC + ci];
            f[c] += w.x * v;
            g[c] += w.y * v;
        }
    }
#pragma unroll
    for (int c = 0; c < RC; c++) {
        rout[(size_t)c * SEQLEN + l] = f[c];
        sk[(size_t)c * SEQLEN + l] = g[c];
    }
}

// ----------------------------------------------------------------
// Kernel 3: hidden = relu(W1 @ relu(skip) + b1)   (32 -> 256, 1x1)
// One thread per (b, l), loops over 256 outputs with W1 in smem.
// ----------------------------------------------------------------
__global__ __launch_bounds__(256)
void k_end1(const float* __restrict__ w1, const float* __restrict__ b1)
{
    __shared__ float sw[OC * RC];   // 32 KB
    __shared__ float sb[OC];
    for (int i = threadIdx.x; i < OC * RC; i += 256) sw[i] = w1[i];
    for (int i = threadIdx.x; i < OC; i += 256) sb[i] = b1[i];
    __syncthreads();

    int base = blockIdx.x * 256 + threadIdx.x;   // over BATCH*SEQLEN
    int b = base / SEQLEN;
    int l = base % SEQLEN;

    float s[RC];
#pragma unroll
    for (int c = 0; c < RC; c++) {
        float v = g_skip[((size_t)b * RC + c) * SEQLEN + l];
        s[c] = v > 0.f ? v : 0.f;
    }
    for (int o = 0; o < OC; o++) {
        float acc = sb[o];
#pragma unroll
        for (int c = 0; c < RC; c += 4) {
            float4 w = *(const float4*)&sw[o * RC + c];
            acc += w.x * s[c] + w.y * s[c + 1] + w.z * s[c + 2] + w.w * s[c + 3];
        }
        g_hidden[((size_t)b * OC + o) * SEQLEN + l] = acc > 0.f ? acc : 0.f;
    }
}

// ----------------------------------------------------------------
// Kernel 4: out = W2 @ hidden + b2   (256 -> 256, 1x1) as tiled SGEMM.
// CTA tile: 64 outputs x 128 positions, K chunks of 32.
// Thread (ty,tx): 4 outputs x 8 positions (l = l0 + tx + 16*j).
// ----------------------------------------------------------------
#define TO 64
#define TL 128
#define TK 32
__global__ __launch_bounds__(256)
void k_end2(float* __restrict__ out,
            const float* __restrict__ w2, const float* __restrict__ b2)
{
    __shared__ float sh[TK][TL];    // 16 KB hidden tile
    __shared__ float swt[TO][TK];   //  8 KB weight tile

    int b = blockIdx.z;
    int o0 = blockIdx.y * TO;
    int l0 = blockIdx.x * TL;
    int tid = threadIdx.x;
    int tx = tid & 15;
    int ty = tid >> 4;

    float acc[4][8];
#pragma unroll
    for (int i = 0; i < 4; i++)
#pragma unroll
        for (int j = 0; j < 8; j++) acc[i][j] = 0.f;

    for (int k0 = 0; k0 < OC; k0 += TK) {
        for (int i = tid; i < TK * TL; i += 256) {
            int kk = i / TL, ll = i % TL;
            sh[kk][ll] = g_hidden[((size_t)b * OC + k0 + kk) * SEQLEN + l0 + ll];
        }
        for (int i = tid; i < TO * TK; i += 256) {
            int oo = i / TK, kk = i % TK;
            swt[oo][kk] = w2[(size_t)(o0 + oo) * OC + k0 + kk];
        }
        __syncthreads();
#pragma unroll
        for (int k = 0; k < TK; k++) {
            float wv[4], hv[8];
#pragma unroll
            for (int i = 0; i < 4; i++) wv[i] = swt[ty * 4 + i][k];
#pragma unroll
            for (int j = 0; j < 8; j++) hv[j] = sh[k][tx + 16 * j];
#pragma unroll
            for (int i = 0; i < 4; i++)
#pragma unroll
                for (int j = 0; j < 8; j++) acc[i][j] += wv[i] * hv[j];
        }
        __syncthreads();
    }
#pragma unroll
    for (int i = 0; i < 4; i++) {
        float bb = b2[o0 + ty * 4 + i];
#pragma unroll
        for (int j = 0; j < 8; j++)
            out[((size_t)b * OC + o0 + ty * 4 + i) * SEQLEN + l0 + tx + 16 * j]
                = acc[i][j] + bb;
    }
}

// ----------------------------------------------------------------
extern "C" void kernel_launch(void* const* d_in, const int* in_sizes, int n_in,
                              void* d_out, int out_size)
{
    const float* x       = (const float*)d_in[0];
    const float* w_start = (const float*)d_in[1];
    const float* b_start = (const float*)d_in[2];
    const float* filt_w  = (const float*)d_in[3];
    const float* filt_b  = (const float*)d_in[4];
    const float* gate_w  = (const float*)d_in[5];
    const float* gate_b  = (const float*)d_in[6];
    const float* res_w   = (const float*)d_in[7];
    const float* res_b   = (const float*)d_in[8];
    const float* skip_w  = (const float*)d_in[9];
    const float* skip_b  = (const float*)d_in[10];
    const float* w_end1  = (const float*)d_in[11];
    const float* b_end1  = (const float*)d_in[12];
    const float* w_end2  = (const float*)d_in[13];
    const float* b_end2  = (const float*)d_in[14];
    float* out = (float*)d_out;

    // start conv + zero skip
    {
        size_t n = (size_t)BATCH * RC * SEQLEN;
        k_start<<<(unsigned)((n + 255) / 256), 256>>>(x, w_start, b_start);
    }

    // 20 gated dilated layers, ping-pong residual
    int ping = 0;
    int nblk = (BATCH * SEQLEN) / 256;
    for (int blk = 0; blk < NBLOCKS; blk++) {
        for (int i = 0; i < NLAYERS; i++) {
            int li = blk * NLAYERS + i;
            int offA, offB;
            if (i == 0) { offA = -1; offB = 0; }
            else { int h = 1 << (i - 1); offA = -h; offB = h; }
            k_layer<<<nblk, 256>>>(ping,
                filt_w + (size_t)li * RC * RC * 2, filt_b + (size_t)li * RC,
                gate_w + (size_t)li * RC * RC * 2, gate_b + (size_t)li * RC,
                res_w  + (size_t)li * RC * RC,     res_b  + (size_t)li * RC,
                skip_w + (size_t)li * RC * RC,     skip_b + (size_t)li * RC,
                offA, offB);
            ping ^= 1;
        }
    }

    // head
    k_end1<<<nblk, 256>>>(w_end1, b_end1);
    dim3 g2(SEQLEN / TL, OC / TO, BATCH);
    k_end2<<<g2, 256>>>(out, w_end2, b_end2);
}

// round 2
// speedup vs baseline: 1.2355x; 1.2355x over previous
#include <cuda_runtime.h>
#include <mma.h>
using namespace nvcuda;

// Problem constants
#define BATCH   4
#define SEQLEN  65536
#define RC      32          // residual / dilation channels
#define OC      256         // output channels
#define NBLOCKS 2
#define NLAYERS 10

// -------- scratch (device globals; no allocation allowed) --------
__device__ float g_resid[2][BATCH * RC * SEQLEN];   // ping-pong residual
__device__ float g_skip[BATCH * RC * SEQLEN];       // skip accumulator
__device__ float g_hidden[(size_t)BATCH * OC * SEQLEN]; // end1 PRE-RELU output

// ----------------------------------------------------------------
// Kernel 1: start conv (1 -> 32, 1x1) + zero skip accumulator.
// ----------------------------------------------------------------
__global__ void k_start(const float* __restrict__ x,
                        const float* __restrict__ w,
                        const float* __restrict__ bias)
{
    size_t idx = (size_t)blockIdx.x * blockDim.x + threadIdx.x;
    if (idx >= (size_t)BATCH * RC * SEQLEN) return;
    int l = (int)(idx % SEQLEN);
    int c = (int)((idx / SEQLEN) % RC);
    int b = (int)(idx / ((size_t)RC * SEQLEN));
    g_resid[0][idx] = w[c] * x[(size_t)b * SEQLEN + l] + bias[c];
    g_skip[idx] = 0.f;
}

// ----------------------------------------------------------------
// Kernel 2: one gated dilated layer. Packed-weight version:
//   wfg[ci][c] = (f_tap0, f_tap1, g_tap0, g_tap1)  -> 1 LDS.128 / 4 FFMA
//   wrs[ci][p] = (res[2p], skip[2p], res[2p+1], skip[2p+1])
// ----------------------------------------------------------------
__global__ __launch_bounds__(256)
void k_layer(int ping,
             const float* __restrict__ fw, const float* __restrict__ fb,
             const float* __restrict__ gw, const float* __restrict__ gb,
             const float* __restrict__ rw, const float* __restrict__ rb,
             const float* __restrict__ sw, const float* __restrict__ sb,
             int offA, int offB)
{
    __shared__ float4 wfg[RC * RC];       // 16 KB, [ci][c]
    __shared__ float4 wrs[RC * RC / 2];   //  8 KB, [ci][c/2]
    __shared__ float sbf[RC], sbg[RC], sbr[RC], sbs[RC];

    int tid = threadIdx.x;
    const float2* fw2 = (const float2*)fw;   // filt_w[c][ci][0..1]
    const float2* gw2 = (const float2*)gw;
    for (int i = tid; i < RC * RC; i += 256) {
        int ci = i >> 5, c = i & 31;
        float2 wf = fw2[c * RC + ci];
        float2 wg = gw2[c * RC + ci];
        wfg[i] = make_float4(wf.x, wf.y, wg.x, wg.y);
    }
    for (int i = tid; i < RC * RC / 2; i += 256) {
        int ci = i >> 4, p = i & 15;
        wrs[i] = make_float4(rw[(2 * p) * RC + ci], sw[(2 * p) * RC + ci],
                             rw[(2 * p + 1) * RC + ci], sw[(2 * p + 1) * RC + ci]);
    }
    if (tid < RC) { sbf[tid] = fb[tid]; sbg[tid] = gb[tid];
                    sbr[tid] = rb[tid]; sbs[tid] = sb[tid]; }
    __syncthreads();

    int base = blockIdx.x * 256 + tid;        // over BATCH*SEQLEN
    int b = base / SEQLEN;
    int l = base % SEQLEN;

    const float* __restrict__ rin = &g_resid[ping][(size_t)b * RC * SEQLEN];
    float* __restrict__ rout = &g_resid[ping ^ 1][(size_t)b * RC * SEQLEN];
    float* __restrict__ sk = &g_skip[(size_t)b * RC * SEQLEN];

    int la = l + offA;
    int lb = l + offB;
    bool va = (la >= 0) && (la < SEQLEN);
    bool vb = (lb >= 0) && (lb < SEQLEN);

    float f[RC], g[RC];
#pragma unroll
    for (int c = 0; c < RC; c++) { f[c] = sbf[c]; g[c] = sbg[c]; }

#pragma unroll 4
    for (int ci = 0; ci < RC; ci++) {
        float rA = va ? rin[(size_t)ci * SEQLEN + la] : 0.f;
        float rB = vb ? rin[(size_t)ci * SEQLEN + lb] : 0.f;
        const float4* wrow = &wfg[ci * RC];
#pragma unroll
        for (int c = 0; c < RC; c++) {
            float4 w = wrow[c];
            f[c] += w.x * rA + w.y * rB;
            g[c] += w.z * rA + w.w * rB;
        }
    }

    // lo stored into g; f becomes residual acc, s[] is skip acc
    float s[RC];
#pragma unroll
    for (int c = 0; c < RC; c++) g[c] *= f[c];
#pragma unroll
    for (int c = 0; c < RC; c++) {
        f[c] = rin[(size_t)c * SEQLEN + l] + sbr[c];
        s[c] = sk[(size_t)c * SEQLEN + l] + sbs[c];
    }
#pragma unroll 4
    for (int ci = 0; ci < RC; ci++) {
        float v = g[ci];
        const float4* wrow = &wrs[ci * (RC / 2)];
#pragma unroll
        for (int p = 0; p < RC / 2; p++) {
            float4 w = wrow[p];
            f[2 * p]     += w.x * v;
            s[2 * p]     += w.y * v;
            f[2 * p + 1] += w.z * v;
            s[2 * p + 1] += w.w * v;
        }
    }
#pragma unroll
    for (int c = 0; c < RC; c++) {
        rout[(size_t)c * SEQLEN + l] = f[c];
        sk[(size_t)c * SEQLEN + l] = s[c];
    }
}

// ----------------------------------------------------------------
// Kernel 3: hidden_pre = W1 @ relu(skip) + b1   (32 -> 256), TF32 wmma.
// Bias folded via extended K: cols 0..31 = W1, col 32 = b1, rest 0;
//                             rows 0..31 = relu(skip), row 32 = 1, rest 0.
// CTA tile 128(M) x 128(N); 8 warps (2x4), warp tile 64x32.
// ----------------------------------------------------------------
#define E1_LDA 44
#define E1_LDB 132
__global__ __launch_bounds__(256)
void k_end1(const float* __restrict__ w1, const float* __restrict__ b1)
{
    __shared__ float As[128 * E1_LDA];   // [m][k], k = 0..39
    __shared__ float Bs[40 * E1_LDB];    // [k][n]

    int b = blockIdx.z;
    int o0 = blockIdx.y * 128;
    int l0 = blockIdx.x * 128;
    int tid = threadIdx.x;

    for (int i = tid; i < 128 * 40; i += 256) {
        int m = i / 40, k = i % 40;
        float v = 0.f;
        if (k < 32) v = w1[(size_t)(o0 + m) * RC + k];
        else if (k == 32) v = b1[o0 + m];
        As[m * E1_LDA + k] = v;
    }
    for (int i = tid; i < 40 * 128; i += 256) {
        int k = i / 128, n = i % 128;
        float v = 0.f;
        if (k < 32) {
            float t = g_skip[((size_t)b * RC + k) * SEQLEN + l0 + n];
            v = t > 0.f ? t : 0.f;
        } else if (k == 32) v = 1.f;
        Bs[k * E1_LDB + n] = v;
    }
    __syncthreads();

    int warp = tid >> 5;
    int wm = warp >> 2;      // 0..1
    int wn = warp & 3;       // 0..3

    wmma::fragment<wmma::accumulator, 16, 16, 8, float> acc[4][2];
#pragma unroll
    for (int mi = 0; mi < 4; mi++)
#pragma unroll
        for (int ni = 0; ni < 2; ni++) wmma::fill_fragment(acc[mi][ni], 0.f);

#pragma unroll
    for (int kf = 0; kf < 5; kf++) {
        wmma::fragment<wmma::matrix_a, 16, 16, 8, wmma::precision::tf32, wmma::row_major> a[4];
        wmma::fragment<wmma::matrix_b, 16, 16, 8, wmma::precision::tf32, wmma::row_major> bf[2];
#pragma unroll
        for (int mi = 0; mi < 4; mi++) {
            wmma::load_matrix_sync(a[mi], &As[(wm * 64 + mi * 16) * E1_LDA + kf * 8], E1_LDA);
#pragma unroll
            for (int t = 0; t < a[mi].num_elements; t++)
                a[mi].x[t] = wmma::__float_to_tf32(a[mi].x[t]);
        }
#pragma unroll
        for (int ni = 0; ni < 2; ni++) {
            wmma::load_matrix_sync(bf[ni], &Bs[(kf * 8) * E1_LDB + wn * 32 + ni * 16], E1_LDB);
#pragma unroll
            for (int t = 0; t < bf[ni].num_elements; t++)
                bf[ni].x[t] = wmma::__float_to_tf32(bf[ni].x[t]);
        }
#pragma unroll
        for (int mi = 0; mi < 4; mi++)
#pragma unroll
            for (int ni = 0; ni < 2; ni++)
                wmma::mma_sync(acc[mi][ni], a[mi], bf[ni], acc[mi][ni]);
    }

#pragma unroll
    for (int mi = 0; mi < 4; mi++)
#pragma unroll
        for (int ni = 0; ni < 2; ni++) {
            float* dst = &g_hidden[((size_t)b * OC + o0 + wm * 64 + mi * 16) * SEQLEN
                                   + l0 + wn * 32 + ni * 16];
            wmma::store_matrix_sync(dst, acc[mi][ni], SEQLEN, wmma::mem_row_major);
        }
}

// ----------------------------------------------------------------
// Kernel 4: out = W2 @ relu(hidden_pre) + b2   (256 -> 256), TF32 wmma.
// K chunks of 16 (16 real chunks + 1 bias chunk).
// ----------------------------------------------------------------
#define E2_LDA 20
#define E2_LDB 132
__global__ __launch_bounds__(256)
void k_end2(float* __restrict__ out,
            const float* __restrict__ w2, const float* __restrict__ b2)
{
    __shared__ float As[128 * E2_LDA];   // [m][k], k = 0..15
    __shared__ float Bs[16 * E2_LDB];    // [k][n]

    int b = blockIdx.z;
    int o0 = blockIdx.y * 128;
    int l0 = blockIdx.x * 128;
    int tid = threadIdx.x;
    int warp = tid >> 5;
    int wm = warp >> 2;
    int wn = warp & 3;

    wmma::fragment<wmma::accumulator, 16, 16, 8, float> acc[4][2];
#pragma unroll
    for (int mi = 0; mi < 4; mi++)
#pragma unroll
        for (int ni = 0; ni < 2; ni++) wmma::fill_fragment(acc[mi][ni], 0.f);

    for (int k0 = 0; k0 < 17; k0++) {
        // fill A tile
        if (k0 < 16) {
            for (int i = tid; i < 128 * 16; i += 256) {
                int m = i >> 4, k = i & 15;
                As[m * E2_LDA + k] = w2[(size_t)(o0 + m) * OC + k0 * 16 + k];
            }
            for (int i = tid; i < 16 * 128; i += 256) {
                int k = i >> 7, n = i & 127;
                float v = g_hidden[((size_t)b * OC + k0 * 16 + k) * SEQLEN + l0 + n];
                Bs[k * E2_LDB + n] = v > 0.f ? v : 0.f;
            }
        } else {
            for (int i = tid; i < 128 * 16; i += 256) {
                int m = i >> 4, k = i & 15;
                As[m * E2_LDA + k] = (k == 0) ? b2[o0 + m] : 0.f;
            }
            for (int i = tid; i < 16 * 128; i += 256) {
                int k = i >> 7, n = i & 127;
                Bs[k * E2_LDB + n] = (k == 0) ? 1.f : 0.f;
            }
        }
        __syncthreads();

#pragma unroll
        for (int kf = 0; kf < 2; kf++) {
            wmma::fragment<wmma::matrix_a, 16, 16, 8, wmma::precision::tf32, wmma::row_major> a[4];
            wmma::fragment<wmma::matrix_b, 16, 16, 8, wmma::precision::tf32, wmma::row_major> bf[2];
#pragma unroll
            for (int mi = 0; mi < 4; mi++) {
                wmma::load_matrix_sync(a[mi], &As[(wm * 64 + mi * 16) * E2_LDA + kf * 8], E2_LDA);
#pragma unroll
                for (int t = 0; t < a[mi].num_elements; t++)
                    a[mi].x[t] = wmma::__float_to_tf32(a[mi].x[t]);
            }
#pragma unroll
            for (int ni = 0; ni < 2; ni++) {
                wmma::load_matrix_sync(bf[ni], &Bs[(kf * 8) * E2_LDB + wn * 32 + ni * 16], E2_LDB);
#pragma unroll
                for (int t = 0; t < bf[ni].num_elements; t++)
                    bf[ni].x[t] = wmma::__float_to_tf32(bf[ni].x[t]);
            }
#pragma unroll
            for (int mi = 0; mi < 4; mi++)
#pragma unroll
                for (int ni = 0; ni < 2; ni++)
                    wmma::mma_sync(acc[mi][ni], a[mi], bf[ni], acc[mi][ni]);
        }
        __syncthreads();
    }

#pragma unroll
    for (int mi = 0; mi < 4; mi++)
#pragma unroll
        for (int ni = 0; ni < 2; ni++) {
            float* dst = &out[((size_t)b * OC + o0 + wm * 64 + mi * 16) * SEQLEN
                              + l0 + wn * 32 + ni * 16];
            wmma::store_matrix_sync(dst, acc[mi][ni], SEQLEN, wmma::mem_row_major);
        }
}

// ----------------------------------------------------------------
extern "C" void kernel_launch(void* const* d_in, const int* in_sizes, int n_in,
                              void* d_out, int out_size)
{
    const float* x       = (const float*)d_in[0];
    const float* w_start = (const float*)d_in[1];
    const float* b_start = (const float*)d_in[2];
    const float* filt_w  = (const float*)d_in[3];
    const float* filt_b  = (const float*)d_in[4];
    const float* gate_w  = (const float*)d_in[5];
    const float* gate_b  = (const float*)d_in[6];
    const float* res_w   = (const float*)d_in[7];
    const float* res_b   = (const float*)d_in[8];
    const float* skip_w  = (const float*)d_in[9];
    const float* skip_b  = (const float*)d_in[10];
    const float* w_end1  = (const float*)d_in[11];
    const float* b_end1  = (const float*)d_in[12];
    const float* w_end2  = (const float*)d_in[13];
    const float* b_end2  = (const float*)d_in[14];
    float* out = (float*)d_out;

    {
        size_t n = (size_t)BATCH * RC * SEQLEN;
        k_start<<<(unsigned)((n + 255) / 256), 256>>>(x, w_start, b_start);
    }

    int ping = 0;
    int nblk = (BATCH * SEQLEN) / 256;
    for (int blk = 0; blk < NBLOCKS; blk++) {
        for (int i = 0; i < NLAYERS; i++) {
            int li = blk * NLAYERS + i;
            int offA, offB;
            if (i == 0) { offA = -1; offB = 0; }
            else { int h = 1 << (i - 1); offA = -h; offB = h; }
            k_layer<<<nblk, 256>>>(ping,
                filt_w + (size_t)li * RC * RC * 2, filt_b + (size_t)li * RC,
                gate_w + (size_t)li * RC * RC * 2, gate_b + (size_t)li * RC,
                res_w  + (size_t)li * RC * RC,     res_b  + (size_t)li * RC,
                skip_w + (size_t)li * RC * RC,     skip_b + (size_t)li * RC,
                offA, offB);
            ping ^= 1;
        }
    }

    dim3 g1(SEQLEN / 128, OC / 128, BATCH);
    k_end1<<<g1, 256>>>(w_end1, b_end1);
    dim3 g2(SEQLEN / 128, OC / 128, BATCH);
    k_end2<<<g2, 256>>>(out, w_end2, b_end2);
}

// round 3
// speedup vs baseline: 1.3841x; 1.1202x over previous
#include <cuda_runtime.h>
#include <mma.h>
using namespace nvcuda;

// Problem constants
#define BATCH   4
#define SEQLEN  65536
#define RC      32
#define OC      256
#define NBLOCKS 2
#define NLAYERS 10

#define TL      256          // positions per CTA in k_layer_tc
#define HLD     776          // halo row stride (floats), mult of 8
#define FGLD    264          // f/g staging row stride, mult of 8
#define WALD    40           // weight A-matrix row stride, mult of 8

// smem layout (floats):
//   halo [32][HLD]          (center at cols 256..511; lo parked at cols 512..767)
//   fg   [64][FGLD]         (GEMM1 then GEMM2 output staging)
//   wA   [3][64][WALD]      (tapA | tapB | res/skip)
//   bias [4][32]
#define SM_HALO 0
#define SM_FG   (32 * HLD)
#define SM_WA   (SM_FG + 64 * FGLD)
#define SM_BIAS (SM_WA + 3 * 64 * WALD)
#define SM_FLOATS (SM_BIAS + 4 * 32)

// -------- scratch (device globals; no allocation allowed) --------
__device__ float g_resid[2][BATCH * RC * SEQLEN];
__device__ float g_skip[BATCH * RC * SEQLEN];
__device__ float g_hidden[(size_t)BATCH * OC * SEQLEN];

// ----------------------------------------------------------------
// Kernel 1: start conv (1 -> 32, 1x1) + zero skip accumulator.
// ----------------------------------------------------------------
__global__ void k_start(const float* __restrict__ x,
                        const float* __restrict__ w,
                        const float* __restrict__ bias)
{
    size_t idx = (size_t)blockIdx.x * blockDim.x + threadIdx.x;
    if (idx >= (size_t)BATCH * RC * SEQLEN) return;
    int l = (int)(idx % SEQLEN);
    int c = (int)((idx / SEQLEN) % RC);
    int b = (int)(idx / ((size_t)RC * SEQLEN));
    g_resid[0][idx] = w[c] * x[(size_t)b * SEQLEN + l] + bias[c];
    g_skip[idx] = 0.f;
}

// ----------------------------------------------------------------
// Kernel 2: one gated dilated layer, TF32 tensor cores.
// CTA = 256 positions of one batch. 8 warps (2m x 4n), warp tile 32x64.
// ----------------------------------------------------------------
__global__ __launch_bounds__(256, 1)
void k_layer_tc(int ping,
                const float* __restrict__ fw, const float* __restrict__ fb,
                const float* __restrict__ gw, const float* __restrict__ gb,
                const float* __restrict__ rw, const float* __restrict__ rb,
                const float* __restrict__ sw, const float* __restrict__ sb,
                int offA, int offB)
{
    extern __shared__ float smem[];
    float* halo = smem + SM_HALO;
    float* fg   = smem + SM_FG;
    float* wA   = smem + SM_WA;
    float* bias = smem + SM_BIAS;

    int tid = threadIdx.x;
    int b = blockIdx.y;
    int l0 = blockIdx.x * TL;

    const float* __restrict__ rin = &g_resid[ping][(size_t)b * RC * SEQLEN];
    float* __restrict__ rout = &g_resid[ping ^ 1][(size_t)b * RC * SEQLEN];
    float* __restrict__ sk = &g_skip[(size_t)b * RC * SEQLEN];

    // --- load weights into A-matrix form: row c = f (or res), row 32+c = g (or skip)
    const float2* fw2 = (const float2*)fw;
    const float2* gw2 = (const float2*)gw;
    for (int i = tid; i < 64 * 32; i += 256) {
        int row = i >> 5, ci = i & 31;
        int c = row & 31;
        if (row < 32) {
            float2 t = fw2[c * 32 + ci];
            wA[0 * 64 * WALD + row * WALD + ci] = t.x;
            wA[1 * 64 * WALD + row * WALD + ci] = t.y;
            wA[2 * 64 * WALD + row * WALD + ci] = rw[c * 32 + ci];
        } else {
            float2 t = gw2[c * 32 + ci];
            wA[0 * 64 * WALD + row * WALD + ci] = t.x;
            wA[1 * 64 * WALD + row * WALD + ci] = t.y;
            wA[2 * 64 * WALD + row * WALD + ci] = sw[c * 32 + ci];
        }
    }
    if (tid < 32) {
        bias[tid]      = fb[tid];
        bias[32 + tid] = gb[tid];
        bias[64 + tid] = rb[tid];
        bias[96 + tid] = sb[tid];
    }

    // --- load residual halo: cols [c0, c1) where col j <-> global l0-256+j
    int c0 = (256 + offA) & ~3;
    int c1 = (512 + offB + 3) & ~3;
    int w4 = (c1 - c0) >> 2;
    for (int i = tid; i < 32 * w4; i += 256) {
        int row = i / w4;
        int col = c0 + ((i - row * w4) << 2);
        int l = l0 - 256 + col;
        float4 v = make_float4(0.f, 0.f, 0.f, 0.f);
        if (l >= 0 && l < SEQLEN)
            v = *(const float4*)&rin[(size_t)row * SEQLEN + l];
        *(float4*)&halo[row * HLD + col] = v;
    }
    __syncthreads();

    int warp = tid >> 5;
    int wm = warp >> 2;   // 0..1
    int wn = warp & 3;    // 0..3

    // ---------------- GEMM1: [f;g] = Wfg @ shifted residuals ----------------
    wmma::fragment<wmma::accumulator, 16, 16, 8, float> acc[2][4];
#pragma unroll
    for (int mi = 0; mi < 2; mi++)
#pragma unroll
        for (int ni = 0; ni < 4; ni++) wmma::fill_fragment(acc[mi][ni], 0.f);

#pragma unroll
    for (int tap = 0; tap < 2; tap++) {
        const float* wAt = wA + tap * 64 * WALD;
        int tapOff = 256 + (tap ? offB : offA);
#pragma unroll
        for (int kf = 0; kf < 4; kf++) {
            wmma::fragment<wmma::matrix_a, 16, 16, 8, wmma::precision::tf32, wmma::row_major> a[2];
            wmma::fragment<wmma::matrix_b, 16, 16, 8, wmma::precision::tf32, wmma::row_major> bf[4];
#pragma unroll
            for (int mi = 0; mi < 2; mi++) {
                wmma::load_matrix_sync(a[mi], &wAt[(wm * 32 + mi * 16) * WALD + kf * 8], WALD);
#pragma unroll
                for (int t = 0; t < a[mi].num_elements; t++)
                    a[mi].x[t] = wmma::__float_to_tf32(a[mi].x[t]);
            }
#pragma unroll
            for (int ni = 0; ni < 4; ni++) {
                wmma::load_matrix_sync(bf[ni], &halo[(kf * 8) * HLD + tapOff + wn * 64 + ni * 16], HLD);
#pragma unroll
                for (int t = 0; t < bf[ni].num_elements; t++)
                    bf[ni].x[t] = wmma::__float_to_tf32(bf[ni].x[t]);
            }
#pragma unroll
            for (int mi = 0; mi < 2; mi++)
#pragma unroll
                for (int ni = 0; ni < 4; ni++)
                    wmma::mma_sync(acc[mi][ni], a[mi], bf[ni], acc[mi][ni]);
        }
    }
#pragma unroll
    for (int mi = 0; mi < 2; mi++)
#pragma unroll
        for (int ni = 0; ni < 4; ni++)
            wmma::store_matrix_sync(&fg[(wm * 32 + mi * 16) * FGLD + wn * 64 + ni * 16],
                                    acc[mi][ni], FGLD, wmma::mem_row_major);
    __syncthreads();

    // ---------------- lo = (f+bf)*(g+bg), parked in halo cols 512.. ----------------
    for (int i = tid; i < 32 * TL; i += 256) {
        int c = i >> 8, n = i & 255;
        float fv = fg[c * FGLD + n] + bias[c];
        float gv = fg[(32 + c) * FGLD + n] + bias[32 + c];
        halo[c * HLD + 512 + n] = fv * gv;
    }
    __syncthreads();

    // ---------------- GEMM2: [res;skip] = Wrs @ lo ----------------
    wmma::fragment<wmma::accumulator, 16, 16, 8, float> acc2[2][4];
#pragma unroll
    for (int mi = 0; mi < 2; mi++)
#pragma unroll
        for (int ni = 0; ni < 4; ni++) wmma::fill_fragment(acc2[mi][ni], 0.f);

    {
        const float* wA2 = wA + 2 * 64 * WALD;
#pragma unroll
        for (int kf = 0; kf < 4; kf++) {
            wmma::fragment<wmma::matrix_a, 16, 16, 8, wmma::precision::tf32, wmma::row_major> a[2];
            wmma::fragment<wmma::matrix_b, 16, 16, 8, wmma::precision::tf32, wmma::row_major> bf[4];
#pragma unroll
            for (int mi = 0; mi < 2; mi++) {
                wmma::load_matrix_sync(a[mi], &wA2[(wm * 32 + mi * 16) * WALD + kf * 8], WALD);
#pragma unroll
                for (int t = 0; t < a[mi].num_elements; t++)
                    a[mi].x[t] = wmma::__float_to_tf32(a[mi].x[t]);
            }
#pragma unroll
            for (int ni = 0; ni < 4; ni++) {
                wmma::load_matrix_sync(bf[ni], &halo[(kf * 8) * HLD + 512 + wn * 64 + ni * 16], HLD);
#pragma unroll
                for (int t = 0; t < bf[ni].num_elements; t++)
                    bf[ni].x[t] = wmma::__float_to_tf32(bf[ni].x[t]);
            }
#pragma unroll
            for (int mi = 0; mi < 2; mi++)
#pragma unroll
                for (int ni = 0; ni < 4; ni++)
                    wmma::mma_sync(acc2[mi][ni], a[mi], bf[ni], acc2[mi][ni]);
        }
    }
#pragma unroll
    for (int mi = 0; mi < 2; mi++)
#pragma unroll
        for (int ni = 0; ni < 4; ni++)
            wmma::store_matrix_sync(&fg[(wm * 32 + mi * 16) * FGLD + wn * 64 + ni * 16],
                                    acc2[mi][ni], FGLD, wmma::mem_row_major);
    __syncthreads();

    // ---------------- residual + skip update (fp32) ----------------
    for (int i = tid; i < 32 * TL; i += 256) {
        int c = i >> 8, n = i & 255;
        size_t gidx = (size_t)c * SEQLEN + l0 + n;
        rout[gidx] = halo[c * HLD + 256 + n] + fg[c * FGLD + n] + bias[64 + c];
        sk[gidx]   = sk[gidx] + fg[(32 + c) * FGLD + n] + bias[96 + c];
    }
}

// ----------------------------------------------------------------
// Kernel 3: hidden_pre = W1 @ relu(skip) + b1   (32 -> 256), TF32 wmma.
// ----------------------------------------------------------------
#define E1_LDA 44
#define E1_LDB 132
__global__ __launch_bounds__(256)
void k_end1(const float* __restrict__ w1, const float* __restrict__ b1)
{
    __shared__ float As[128 * E1_LDA];
    __shared__ float Bs[40 * E1_LDB];

    int b = blockIdx.z;
    int o0 = blockIdx.y * 128;
    int l0 = blockIdx.x * 128;
    int tid = threadIdx.x;

    for (int i = tid; i < 128 * 40; i += 256) {
        int m = i / 40, k = i % 40;
        float v = 0.f;
        if (k < 32) v = w1[(size_t)(o0 + m) * RC + k];
        else if (k == 32) v = b1[o0 + m];
        As[m * E1_LDA + k] = v;
    }
    for (int i = tid; i < 40 * 128; i += 256) {
        int k = i / 128, n = i % 128;
        float v = 0.f;
        if (k < 32) {
            float t = g_skip[((size_t)b * RC + k) * SEQLEN + l0 + n];
            v = t > 0.f ? t : 0.f;
        } else if (k == 32) v = 1.f;
        Bs[k * E1_LDB + n] = v;
    }
    __syncthreads();

    int warp = tid >> 5;
    int wm = warp >> 2;
    int wn = warp & 3;

    wmma::fragment<wmma::accumulator, 16, 16, 8, float> acc[4][2];
#pragma unroll
    for (int mi = 0; mi < 4; mi++)
#pragma unroll
        for (int ni = 0; ni < 2; ni++) wmma::fill_fragment(acc[mi][ni], 0.f);

#pragma unroll
    for (int kf = 0; kf < 5; kf++) {
        wmma::fragment<wmma::matrix_a, 16, 16, 8, wmma::precision::tf32, wmma::row_major> a[4];
        wmma::fragment<wmma::matrix_b, 16, 16, 8, wmma::precision::tf32, wmma::row_major> bf[2];
#pragma unroll
        for (int mi = 0; mi < 4; mi++) {
            wmma::load_matrix_sync(a[mi], &As[(wm * 64 + mi * 16) * E1_LDA + kf * 8], E1_LDA);
#pragma unroll
            for (int t = 0; t < a[mi].num_elements; t++)
                a[mi].x[t] = wmma::__float_to_tf32(a[mi].x[t]);
        }
#pragma unroll
        for (int ni = 0; ni < 2; ni++) {
            wmma::load_matrix_sync(bf[ni], &Bs[(kf * 8) * E1_LDB + wn * 32 + ni * 16], E1_LDB);
#pragma unroll
            for (int t = 0; t < bf[ni].num_elements; t++)
                bf[ni].x[t] = wmma::__float_to_tf32(bf[ni].x[t]);
        }
#pragma unroll
        for (int mi = 0; mi < 4; mi++)
#pragma unroll
            for (int ni = 0; ni < 2; ni++)
                wmma::mma_sync(acc[mi][ni], a[mi], bf[ni], acc[mi][ni]);
    }

#pragma unroll
    for (int mi = 0; mi < 4; mi++)
#pragma unroll
        for (int ni = 0; ni < 2; ni++) {
            float* dst = &g_hidden[((size_t)b * OC + o0 + wm * 64 + mi * 16) * SEQLEN
                                   + l0 + wn * 32 + ni * 16];
            wmma::store_matrix_sync(dst, acc[mi][ni], SEQLEN, wmma::mem_row_major);
        }
}

// ----------------------------------------------------------------
// Kernel 4: out = W2 @ relu(hidden_pre) + b2   (256 -> 256), TF32 wmma.
// ----------------------------------------------------------------
#define E2_LDA 20
#define E2_LDB 132
__global__ __launch_bounds__(256)
void k_end2(float* __restrict__ out,
            const float* __restrict__ w2, const float* __restrict__ b2)
{
    __shared__ float As[128 * E2_LDA];
    __shared__ float Bs[16 * E2_LDB];

    int b = blockIdx.z;
    int o0 = blockIdx.y * 128;
    int l0 = blockIdx.x * 128;
    int tid = threadIdx.x;
    int warp = tid >> 5;
    int wm = warp >> 2;
    int wn = warp & 3;

    wmma::fragment<wmma::accumulator, 16, 16, 8, float> acc[4][2];
#pragma unroll
    for (int mi = 0; mi < 4; mi++)
#pragma unroll
        for (int ni = 0; ni < 2; ni++) wmma::fill_fragment(acc[mi][ni], 0.f);

    for (int k0 = 0; k0 < 17; k0++) {
        if (k0 < 16) {
            for (int i = tid; i < 128 * 16; i += 256) {
                int m = i >> 4, k = i & 15;
                As[m * E2_LDA + k] = w2[(size_t)(o0 + m) * OC + k0 * 16 + k];
            }
            for (int i = tid; i < 16 * 128; i += 256) {
                int k = i >> 7, n = i & 127;
                float v = g_hidden[((size_t)b * OC + k0 * 16 + k) * SEQLEN + l0 + n];
                Bs[k * E2_LDB + n] = v > 0.f ? v : 0.f;
            }
        } else {
            for (int i = tid; i < 128 * 16; i += 256) {
                int m = i >> 4, k = i & 15;
                As[m * E2_LDA + k] = (k == 0) ? b2[o0 + m] : 0.f;
            }
            for (int i = tid; i < 16 * 128; i += 256) {
                int k = i >> 7, n = i & 127;
                Bs[k * E2_LDB + n] = (k == 0) ? 1.f : 0.f;
            }
        }
        __syncthreads();

#pragma unroll
        for (int kf = 0; kf < 2; kf++) {
            wmma::fragment<wmma::matrix_a, 16, 16, 8, wmma::precision::tf32, wmma::row_major> a[4];
            wmma::fragment<wmma::matrix_b, 16, 16, 8, wmma::precision::tf32, wmma::row_major> bf[2];
#pragma unroll
            for (int mi = 0; mi < 4; mi++) {
                wmma::load_matrix_sync(a[mi], &As[(wm * 64 + mi * 16) * E2_LDA + kf * 8], E2_LDA);
#pragma unroll
                for (int t = 0; t < a[mi].num_elements; t++)
                    a[mi].x[t] = wmma::__float_to_tf32(a[mi].x[t]);
            }
#pragma unroll
            for (int ni = 0; ni < 2; ni++) {
                wmma::load_matrix_sync(bf[ni], &Bs[(kf * 8) * E2_LDB + wn * 32 + ni * 16], E2_LDB);
#pragma unroll
                for (int t = 0; t < bf[ni].num_elements; t++)
                    bf[ni].x[t] = wmma::__float_to_tf32(bf[ni].x[t]);
            }
#pragma unroll
            for (int mi = 0; mi < 4; mi++)
#pragma unroll
                for (int ni = 0; ni < 2; ni++)
                    wmma::mma_sync(acc[mi][ni], a[mi], bf[ni], acc[mi][ni]);
        }
        __syncthreads();
    }

#pragma unroll
    for (int mi = 0; mi < 4; mi++)
#pragma unroll
        for (int ni = 0; ni < 2; ni++) {
            float* dst = &out[((size_t)b * OC + o0 + wm * 64 + mi * 16) * SEQLEN
                              + l0 + wn * 32 + ni * 16];
            wmma::store_matrix_sync(dst, acc[mi][ni], SEQLEN, wmma::mem_row_major);
        }
}

// ----------------------------------------------------------------
extern "C" void kernel_launch(void* const* d_in, const int* in_sizes, int n_in,
                              void* d_out, int out_size)
{
    const float* x       = (const float*)d_in[0];
    const float* w_start = (const float*)d_in[1];
    const float* b_start = (const float*)d_in[2];
    const float* filt_w  = (const float*)d_in[3];
    const float* filt_b  = (const float*)d_in[4];
    const float* gate_w  = (const float*)d_in[5];
    const float* gate_b  = (const float*)d_in[6];
    const float* res_w   = (const float*)d_in[7];
    const float* res_b   = (const float*)d_in[8];
    const float* skip_w  = (const float*)d_in[9];
    const float* skip_b  = (const float*)d_in[10];
    const float* w_end1  = (const float*)d_in[11];
    const float* b_end1  = (const float*)d_in[12];
    const float* w_end2  = (const float*)d_in[13];
    const float* b_end2  = (const float*)d_in[14];
    float* out = (float*)d_out;

    static int smem_set = 0;
    if (!smem_set) {
        cudaFuncSetAttribute(k_layer_tc, cudaFuncAttributeMaxDynamicSharedMemorySize,
                             SM_FLOATS * (int)sizeof(float));
        smem_set = 1;
    }

    {
        size_t n = (size_t)BATCH * RC * SEQLEN;
        k_start<<<(unsigned)((n + 255) / 256), 256>>>(x, w_start, b_start);
    }

    int ping = 0;
    dim3 gl(SEQLEN / TL, BATCH);
    for (int blk = 0; blk < NBLOCKS; blk++) {
        for (int i = 0; i < NLAYERS; i++) {
            int li = blk * NLAYERS + i;
            int offA, offB;
            if (i == 0) { offA = -1; offB = 0; }
            else { int h = 1 << (i - 1); offA = -h; offB = h; }
            k_layer_tc<<<gl, 256, SM_FLOATS * sizeof(float)>>>(ping,
                filt_w + (size_t)li * RC * RC * 2, filt_b + (size_t)li * RC,
                gate_w + (size_t)li * RC * RC * 2, gate_b + (size_t)li * RC,
                res_w  + (size_t)li * RC * RC,     res_b  + (size_t)li * RC,
                skip_w + (size_t)li * RC * RC,     skip_b + (size_t)li * RC,
                offA, offB);
            ping ^= 1;
        }
    }

    dim3 g1(SEQLEN / 128, OC / 128, BATCH);
    k_end1<<<g1, 256>>>(w_end1, b_end1);
    dim3 g2(SEQLEN / 128, OC / 128, BATCH);
    k_end2<<<g2, 256>>>(out, w_end2, b_end2);
}

// round 5
// speedup vs baseline: 1.7741x; 1.2818x over previous
#include <cuda_runtime.h>
#include <mma.h>
using namespace nvcuda;

// Problem constants
#define BATCH   4
#define SEQLEN  65536
#define RC      32
#define OC      256
#define NBLOCKS 2
#define NLAYERS 10

#define TL      128           // positions per CTA in k_layer_tc
#define FGLD    132           // f/g + output staging row stride
#define WALD    40            // weight A row stride
// fixed smem part (floats): fg[64][FGLD] + lo[32][FGLD] + wA[3][64][WALD] + bias[128]
#define SM_FIXED (64 * FGLD + 32 * FGLD + 3 * 64 * WALD + 128)

// -------- scratch (device globals; no allocation allowed) --------
__device__ float g_resid[2][BATCH * RC * SEQLEN];
__device__ float g_skip[BATCH * RC * SEQLEN];
__device__ float g_hidden[(size_t)BATCH * OC * SEQLEN];

// ----------------------------------------------------------------
// Kernel 1: start conv (1 -> 32, 1x1).
// ----------------------------------------------------------------
__global__ void k_start(const float* __restrict__ x,
                        const float* __restrict__ w,
                        const float* __restrict__ bias)
{
    size_t idx = (size_t)blockIdx.x * blockDim.x + threadIdx.x;
    if (idx >= (size_t)BATCH * RC * SEQLEN) return;
    int l = (int)(idx % SEQLEN);
    int c = (int)((idx / SEQLEN) % RC);
    int b = (int)(idx / ((size_t)RC * SEQLEN));
    g_resid[0][idx] = w[c] * x[(size_t)b * SEQLEN + l] + bias[c];
}

// ----------------------------------------------------------------
// Kernel 2: one gated dilated layer, TF32 wmma, warp-local phases.
// CTA = 128 positions. 8 warps, each owns a 16-col slice and all 64 rows.
// PAD is the halo center offset, rounded up to a multiple of 4 so all
// float4 halo loads are aligned (l0 - PAD + 4k is a multiple of 4).
// ----------------------------------------------------------------
__global__ __launch_bounds__(256, 2)
void k_layer_tc(int ping,
                const float* __restrict__ fw, const float* __restrict__ fb,
                const float* __restrict__ gw, const float* __restrict__ gb,
                const float* __restrict__ rw, const float* __restrict__ rb,
                const float* __restrict__ sw, const float* __restrict__ sb,
                int offA, int offB, int PAD, int HS, int skipInit)
{
    extern __shared__ float smem[];
    float* halo = smem;                 // [32][HS], col PAD+n <-> global l0+n
    float* fg   = smem + 32 * HS;       // [64][FGLD]
    float* lo   = fg + 64 * FGLD;       // [32][FGLD]
    float* wA   = lo + 32 * FGLD;       // [3][64][WALD]
    float* bias = wA + 3 * 64 * WALD;   // [128]

    int tid = threadIdx.x;
    int b = blockIdx.y;
    int l0 = blockIdx.x * TL;

    const float* __restrict__ rin = &g_resid[ping][(size_t)b * RC * SEQLEN];
    float* __restrict__ rout = &g_resid[ping ^ 1][(size_t)b * RC * SEQLEN];
    float* __restrict__ sk = &g_skip[(size_t)b * RC * SEQLEN];

    // --- weights -> A-matrix form (row c: filt/res, row 32+c: gate/skip)
    const float2* fw2 = (const float2*)fw;
    const float2* gw2 = (const float2*)gw;
    for (int i = tid; i < 64 * 32; i += 256) {
        int row = i >> 5, ci = i & 31;
        int c = row & 31;
        if (row < 32) {
            float2 t = fw2[c * 32 + ci];
            wA[0 * 64 * WALD + row * WALD + ci] = t.x;
            wA[1 * 64 * WALD + row * WALD + ci] = t.y;
            wA[2 * 64 * WALD + row * WALD + ci] = rw[c * 32 + ci];
        } else {
            float2 t = gw2[c * 32 + ci];
            wA[0 * 64 * WALD + row * WALD + ci] = t.x;
            wA[1 * 64 * WALD + row * WALD + ci] = t.y;
            wA[2 * 64 * WALD + row * WALD + ci] = sw[c * 32 + ci];
        }
    }
    if (tid < 32) {
        bias[tid]      = fb[tid];
        bias[32 + tid] = gb[tid];
        bias[64 + tid] = rb[tid];
        bias[96 + tid] = sb[tid];
    }

    // --- residual halo load (zero-padded OOB); PAD and l0 are multiples of 4
    {
        int c0 = (PAD + offA) & ~3;                  // >= 0, multiple of 4
        int c1 = (PAD + TL + offB + 4) & ~3;         // exclusive upper bound
        int w4 = (c1 - c0) >> 2;
        for (int i = tid; i < 32 * w4; i += 256) {
            int row = i / w4;
            int col = c0 + ((i - row * w4) << 2);
            int l = l0 - PAD + col;                  // multiple of 4
            float4 v = make_float4(0.f, 0.f, 0.f, 0.f);
            if (l >= 0 && l < SEQLEN)
                v = *(const float4*)&rin[(size_t)row * SEQLEN + l];
            *(float4*)&halo[row * HS + col] = v;
        }
    }
    __syncthreads();

    int warp = tid >> 5;
    int lane = tid & 31;
    int n0 = warp * 16;                 // this warp's column slice
    int lcol = n0 + (lane & 15);        // elementwise: lane's column
    int cbase = (lane >> 4) * 16;       // elementwise: lane's row half

    // ---------------- GEMM1: [f;g](64) = Wfg @ shifted residual ----------------
    wmma::fragment<wmma::accumulator, 16, 16, 8, float> acc[4];
#pragma unroll
    for (int mi = 0; mi < 4; mi++) wmma::fill_fragment(acc[mi], 0.f);

#pragma unroll
    for (int tap = 0; tap < 2; tap++) {
        const float* wAt = wA + tap * 64 * WALD;
        int tapOff = PAD + (tap ? offB : offA) + n0;
#pragma unroll
        for (int kf = 0; kf < 4; kf++) {
            wmma::fragment<wmma::matrix_a, 16, 16, 8, wmma::precision::tf32, wmma::row_major> a;
            wmma::fragment<wmma::matrix_b, 16, 16, 8, wmma::precision::tf32, wmma::row_major> bf;
            wmma::load_matrix_sync(bf, &halo[(kf * 8) * HS + tapOff], HS);
#pragma unroll
            for (int t = 0; t < bf.num_elements; t++)
                bf.x[t] = wmma::__float_to_tf32(bf.x[t]);
#pragma unroll
            for (int mi = 0; mi < 4; mi++) {
                wmma::load_matrix_sync(a, &wAt[(mi * 16) * WALD + kf * 8], WALD);
#pragma unroll
                for (int t = 0; t < a.num_elements; t++)
                    a.x[t] = wmma::__float_to_tf32(a.x[t]);
                wmma::mma_sync(acc[mi], a, bf, acc[mi]);
            }
        }
    }
#pragma unroll
    for (int mi = 0; mi < 4; mi++)
        wmma::store_matrix_sync(&fg[(mi * 16) * FGLD + n0], acc[mi], FGLD, wmma::mem_row_major);
    __syncwarp();

    // ---------------- lo = (f+bf)*(g+bg)  (warp-local elementwise) ----------------
#pragma unroll
    for (int cc = 0; cc < 16; cc++) {
        int c = cbase + cc;
        float fv = fg[c * FGLD + lcol] + bias[c];
        float gv = fg[(32 + c) * FGLD + lcol] + bias[32 + c];
        lo[c * FGLD + lcol] = fv * gv;
    }
    __syncwarp();

    // ---------------- GEMM2: [res;skip] = Wrs @ lo ----------------
#pragma unroll
    for (int mi = 0; mi < 4; mi++) wmma::fill_fragment(acc[mi], 0.f);
    {
        const float* wA2 = wA + 2 * 64 * WALD;
#pragma unroll
        for (int kf = 0; kf < 4; kf++) {
            wmma::fragment<wmma::matrix_a, 16, 16, 8, wmma::precision::tf32, wmma::row_major> a;
            wmma::fragment<wmma::matrix_b, 16, 16, 8, wmma::precision::tf32, wmma::row_major> bf;
            wmma::load_matrix_sync(bf, &lo[(kf * 8) * FGLD + n0], FGLD);
#pragma unroll
            for (int t = 0; t < bf.num_elements; t++)
                bf.x[t] = wmma::__float_to_tf32(bf.x[t]);
#pragma unroll
            for (int mi = 0; mi < 4; mi++) {
                wmma::load_matrix_sync(a, &wA2[(mi * 16) * WALD + kf * 8], WALD);
#pragma unroll
                for (int t = 0; t < a.num_elements; t++)
                    a.x[t] = wmma::__float_to_tf32(a.x[t]);
                wmma::mma_sync(acc[mi], a, bf, acc[mi]);
            }
        }
    }
#pragma unroll
    for (int mi = 0; mi < 4; mi++)
        wmma::store_matrix_sync(&fg[(mi * 16) * FGLD + n0], acc[mi], FGLD, wmma::mem_row_major);
    __syncwarp();

    // ---------------- residual + skip epilogue (fp32, warp-local) ----------------
#pragma unroll
    for (int cc = 0; cc < 16; cc++) {
        int c = cbase + cc;
        size_t gidx = (size_t)c * SEQLEN + l0 + lcol;
        float rv = halo[c * HS + PAD + lcol] + fg[c * FGLD + lcol] + bias[64 + c];
        float sv = fg[(32 + c) * FGLD + lcol] + bias[96 + c];
        if (!skipInit) sv += sk[gidx];
        rout[gidx] = rv;
        sk[gidx] = sv;
    }
}

// ----------------------------------------------------------------
// Kernel 3: hidden_pre = W1 @ relu(skip) + b1   (32 -> 256), TF32 wmma.
// ----------------------------------------------------------------
#define E1_LDA 44
#define E1_LDB 132
__global__ __launch_bounds__(256)
void k_end1(const float* __restrict__ w1, const float* __restrict__ b1)
{
    __shared__ float As[128 * E1_LDA];
    __shared__ float Bs[40 * E1_LDB];

    int b = blockIdx.z;
    int o0 = blockIdx.y * 128;
    int l0 = blockIdx.x * 128;
    int tid = threadIdx.x;

    for (int i = tid; i < 128 * 40; i += 256) {
        int m = i / 40, k = i % 40;
        float v = 0.f;
        if (k < 32) v = w1[(size_t)(o0 + m) * RC + k];
        else if (k == 32) v = b1[o0 + m];
        As[m * E1_LDA + k] = v;
    }
    for (int i = tid; i < 40 * 128; i += 256) {
        int k = i / 128, n = i % 128;
        float v = 0.f;
        if (k < 32) {
            float t = g_skip[((size_t)b * RC + k) * SEQLEN + l0 + n];
            v = t > 0.f ? t : 0.f;
        } else if (k == 32) v = 1.f;
        Bs[k * E1_LDB + n] = v;
    }
    __syncthreads();

    int warp = tid >> 5;
    int wm = warp >> 2;
    int wn = warp & 3;

    wmma::fragment<wmma::accumulator, 16, 16, 8, float> acc[4][2];
#pragma unroll
    for (int mi = 0; mi < 4; mi++)
#pragma unroll
        for (int ni = 0; ni < 2; ni++) wmma::fill_fragment(acc[mi][ni], 0.f);

#pragma unroll
    for (int kf = 0; kf < 5; kf++) {
        wmma::fragment<wmma::matrix_a, 16, 16, 8, wmma::precision::tf32, wmma::row_major> a[4];
        wmma::fragment<wmma::matrix_b, 16, 16, 8, wmma::precision::tf32, wmma::row_major> bf[2];
#pragma unroll
        for (int mi = 0; mi < 4; mi++) {
            wmma::load_matrix_sync(a[mi], &As[(wm * 64 + mi * 16) * E1_LDA + kf * 8], E1_LDA);
#pragma unroll
            for (int t = 0; t < a[mi].num_elements; t++)
                a[mi].x[t] = wmma::__float_to_tf32(a[mi].x[t]);
        }
#pragma unroll
        for (int ni = 0; ni < 2; ni++) {
            wmma::load_matrix_sync(bf[ni], &Bs[(kf * 8) * E1_LDB + wn * 32 + ni * 16], E1_LDB);
#pragma unroll
            for (int t = 0; t < bf[ni].num_elements; t++)
                bf[ni].x[t] = wmma::__float_to_tf32(bf[ni].x[t]);
        }
#pragma unroll
        for (int mi = 0; mi < 4; mi++)
#pragma unroll
            for (int ni = 0; ni < 2; ni++)
                wmma::mma_sync(acc[mi][ni], a[mi], bf[ni], acc[mi][ni]);
    }

#pragma unroll
    for (int mi = 0; mi < 4; mi++)
#pragma unroll
        for (int ni = 0; ni < 2; ni++) {
            float* dst = &g_hidden[((size_t)b * OC + o0 + wm * 64 + mi * 16) * SEQLEN
                                   + l0 + wn * 32 + ni * 16];
            wmma::store_matrix_sync(dst, acc[mi][ni], SEQLEN, wmma::mem_row_major);
        }
}

// ----------------------------------------------------------------
// Kernel 4: out = W2 @ relu(hidden_pre) + b2   (256 -> 256), TF32 wmma.
// ----------------------------------------------------------------
#define E2_LDA 20
#define E2_LDB 132
__global__ __launch_bounds__(256)
void k_end2(float* __restrict__ out,
            const float* __restrict__ w2, const float* __restrict__ b2)
{
    __shared__ float As[128 * E2_LDA];
    __shared__ float Bs[16 * E2_LDB];

    int b = blockIdx.z;
    int o0 = blockIdx.y * 128;
    int l0 = blockIdx.x * 128;
    int tid = threadIdx.x;
    int warp = tid >> 5;
    int wm = warp >> 2;
    int wn = warp & 3;

    wmma::fragment<wmma::accumulator, 16, 16, 8, float> acc[4][2];
#pragma unroll
    for (int mi = 0; mi < 4; mi++)
#pragma unroll
        for (int ni = 0; ni < 2; ni++) wmma::fill_fragment(acc[mi][ni], 0.f);

    for (int k0 = 0; k0 < 17; k0++) {
        if (k0 < 16) {
            for (int i = tid; i < 128 * 16; i += 256) {
                int m = i >> 4, k = i & 15;
                As[m * E2_LDA + k] = w2[(size_t)(o0 + m) * OC + k0 * 16 + k];
            }
            for (int i = tid; i < 16 * 128; i += 256) {
                int k = i >> 7, n = i & 127;
                float v = g_hidden[((size_t)b * OC + k0 * 16 + k) * SEQLEN + l0 + n];
                Bs[k * E2_LDB + n] = v > 0.f ? v : 0.f;
            }
        } else {
            for (int i = tid; i < 128 * 16; i += 256) {
                int m = i >> 4, k = i & 15;
                As[m * E2_LDA + k] = (k == 0) ? b2[o0 + m] : 0.f;
            }
            for (int i = tid; i < 16 * 128; i += 256) {
                int k = i >> 7, n = i & 127;
                Bs[k * E2_LDB + n] = (k == 0) ? 1.f : 0.f;
            }
        }
        __syncthreads();

#pragma unroll
        for (int kf = 0; kf < 2; kf++) {
            wmma::fragment<wmma::matrix_a, 16, 16, 8, wmma::precision::tf32, wmma::row_major> a[4];
            wmma::fragment<wmma::matrix_b, 16, 16, 8, wmma::precision::tf32, wmma::row_major> bf[2];
#pragma unroll
            for (int mi = 0; mi < 4; mi++) {
                wmma::load_matrix_sync(a[mi], &As[(wm * 64 + mi * 16) * E2_LDA + kf * 8], E2_LDA);
#pragma unroll
                for (int t = 0; t < a[mi].num_elements; t++)
                    a[mi].x[t] = wmma::__float_to_tf32(a[mi].x[t]);
            }
#pragma unroll
            for (int ni = 0; ni < 2; ni++) {
                wmma::load_matrix_sync(bf[ni], &Bs[(kf * 8) * E2_LDB + wn * 32 + ni * 16], E2_LDB);
#pragma unroll
                for (int t = 0; t < bf[ni].num_elements; t++)
                    bf[ni].x[t] = wmma::__float_to_tf32(bf[ni].x[t]);
            }
#pragma unroll
            for (int mi = 0; mi < 4; mi++)
#pragma unroll
                for (int ni = 0; ni < 2; ni++)
                    wmma::mma_sync(acc[mi][ni], a[mi], bf[ni], acc[mi][ni]);
        }
        __syncthreads();
    }

#pragma unroll
    for (int mi = 0; mi < 4; mi++)
#pragma unroll
        for (int ni = 0; ni < 2; ni++) {
            float* dst = &out[((size_t)b * OC + o0 + wm * 64 + mi * 16) * SEQLEN
                              + l0 + wn * 32 + ni * 16];
            wmma::store_matrix_sync(dst, acc[mi][ni], SEQLEN, wmma::mem_row_major);
        }
}

// ----------------------------------------------------------------
extern "C" void kernel_launch(void* const* d_in, const int* in_sizes, int n_in,
                              void* d_out, int out_size)
{
    const float* x       = (const float*)d_in[0];
    const float* w_start = (const float*)d_in[1];
    const float* b_start = (const float*)d_in[2];
    const float* filt_w  = (const float*)d_in[3];
    const float* filt_b  = (const float*)d_in[4];
    const float* gate_w  = (const float*)d_in[5];
    const float* gate_b  = (const float*)d_in[6];
    const float* res_w   = (const float*)d_in[7];
    const float* res_b   = (const float*)d_in[8];
    const float* skip_w  = (const float*)d_in[9];
    const float* skip_b  = (const float*)d_in[10];
    const float* w_end1  = (const float*)d_in[11];
    const float* b_end1  = (const float*)d_in[12];
    const float* w_end2  = (const float*)d_in[13];
    const float* b_end2  = (const float*)d_in[14];
    float* out = (float*)d_out;

    static int smem_set = 0;
    if (!smem_set) {
        int hsMax = (TL + 2 * 256 + 11) & ~3;
        cudaFuncSetAttribute(k_layer_tc, cudaFuncAttributeMaxDynamicSharedMemorySize,
                             (SM_FIXED + 32 * hsMax) * (int)sizeof(float));
        smem_set = 1;
    }

    {
        size_t n = (size_t)BATCH * RC * SEQLEN;
        k_start<<<(unsigned)((n + 255) / 256), 256>>>(x, w_start, b_start);
    }

    int ping = 0;
    dim3 gl(SEQLEN / TL, BATCH);
    for (int blk = 0; blk < NBLOCKS; blk++) {
        for (int i = 0; i < NLAYERS; i++) {
            int li = blk * NLAYERS + i;
            int offA, offB;
            if (i == 0) { offA = -1; offB = 0; }
            else { int h = 1 << (i - 1); offA = -h; offB = h; }
            int CO = -offA > offB ? -offA : offB;
            int PAD = (CO + 3) & ~3;                 // 4-aligned halo center
            int HS = (TL + 2 * PAD + 11) & ~3;
            int smemBytes = (SM_FIXED + 32 * HS) * (int)sizeof(float);
            k_layer_tc<<<gl, 256, smemBytes>>>(ping,
                filt_w + (size_t)li * RC * RC * 2, filt_b + (size_t)li * RC,
                gate_w + (size_t)li * RC * RC * 2, gate_b + (size_t)li * RC,
                res_w  + (size_t)li * RC * RC,     res_b  + (size_t)li * RC,
                skip_w + (size_t)li * RC * RC,     skip_b + (size_t)li * RC,
                offA, offB, PAD, HS, (li == 0) ? 1 : 0);
            ping ^= 1;
        }
    }

    dim3 g1(SEQLEN / 128, OC / 128, BATCH);
    k_end1<<<g1, 256>>>(w_end1, b_end1);
    dim3 g2(SEQLEN / 128, OC / 128, BATCH);
    k_end2<<<g2, 256>>>(out, w_end2, b_end2);
}